// round 1
// baseline (speedup 1.0000x reference)
#include <cuda_runtime.h>
#include <cuda_bf16.h>
#include <cstdint>

#define NPTS 500000
#define NCLU 40000
#define DFEAT 64
#define DLOG 20
#define DPTS 4
#define DPROJ 3
#define KRAW 91            // 64+20+4+3
#define DOUT 128
#define SUMS_STRIDE 96     // 91 sums + count at [91], padded to 96 (16B multiple)
#define EPS 1e-5f
#define SLOPE 0.1f

// ---------------- device scratch (static, allocation-free) ----------------
__device__ float g_sums[2ull * NCLU * SUMS_STRIDE];   // per (side,cluster): sums[0..90], count[91]
__device__ float g_hc[2ull * NCLU * DOUT];            // W2 @ mean + b  per (side,cluster)
__device__ float g_h[(size_t)NPTS * DOUT];            // pre-BN activations
__device__ float g_bnsum[DOUT];
__device__ float g_bnsq[DOUT];
__device__ float g_scale[DOUT];
__device__ float g_shift[DOUT];
__device__ int   g_maskmode;                          // 0=uint8(bool), 1=float32, 2=int32

// ---------------- helpers ----------------
__device__ __forceinline__ unsigned long long fma2(unsigned long long a,
                                                   unsigned long long b,
                                                   unsigned long long c) {
    unsigned long long d;
    asm("fma.rn.f32x2 %0, %1, %2, %3;" : "=l"(d) : "l"(a), "l"(b), "l"(c));
    return d;
}

__device__ __forceinline__ void red4(float* p, float a, float b, float c, float d) {
    asm volatile("red.global.add.v4.f32 [%0], {%1, %2, %3, %4};"
                 :: "l"(p), "f"(a), "f"(b), "f"(c), "f"(d) : "memory");
}

__device__ __forceinline__ int get_fg(const void* m, int i, int mode) {
    if (mode == 0) return ((const unsigned char*)m)[i] != 0;
    if (mode == 1) return ((const float*)m)[i] != 0.0f;
    return ((const int*)m)[i] != 0;
}

// ---------------- 0: probe fg_mask dtype ----------------
// bool(u8): bytes at offset 1 (mod 4) are mask values -> OR != 0 (w.h.p.)
// float32 (0.0/1.0): byte1 == 0 always, byte3 == 0x3F for 1.0
// int32 (0/1): byte1 == 0 and byte3 == 0
__global__ void probe_mask_kernel(const unsigned char* m) {
    __shared__ int s1, s3;
    if (threadIdx.x == 0) { s1 = 0; s3 = 0; }
    __syncthreads();
    int o1 = 0, o3 = 0;
    for (int i = threadIdx.x; i < 16384; i += blockDim.x) {  // 64KB window (safe for all dtypes)
        o1 |= m[i * 4 + 1];
        o3 |= m[i * 4 + 3];
    }
    atomicOr(&s1, o1);
    atomicOr(&s3, o3);
    __syncthreads();
    if (threadIdx.x == 0) g_maskmode = s1 ? 0 : (s3 ? 1 : 2);
}

// ---------------- 1: zero scratch ----------------
__global__ void zero_kernel() {
    size_t gid = (size_t)blockIdx.x * blockDim.x + threadIdx.x;
    const size_t n4 = (size_t)2 * NCLU * SUMS_STRIDE / 4;
    float4 z = make_float4(0.f, 0.f, 0.f, 0.f);
    if (gid < n4) reinterpret_cast<float4*>(g_sums)[gid] = z;
    if (gid < 32) reinterpret_cast<float4*>(g_bnsum)[gid] = z;
    else if (gid < 64) reinterpret_cast<float4*>(g_bnsq)[gid - 32] = z;
}

// ---------------- 2: scatter segment sums ----------------
__global__ void scatter_kernel(const float* __restrict__ feat,
                               const float* __restrict__ logit,
                               const float* __restrict__ pts,
                               const float* __restrict__ proj,
                               const int* __restrict__ idx,
                               const void* __restrict__ mask) {
    int i = blockIdx.x * blockDim.x + threadIdx.x;
    if (i >= NPTS) return;
    int mode = g_maskmode;
    int fg = get_fg(mask, i, mode);
    int cs = (fg ? 0 : NCLU) + idx[i];

    float v[92];
    const float4* f4 = reinterpret_cast<const float4*>(feat + (size_t)i * DFEAT);
#pragma unroll
    for (int j = 0; j < 16; ++j) {
        float4 t = f4[j];
        v[4 * j + 0] = t.x; v[4 * j + 1] = t.y; v[4 * j + 2] = t.z; v[4 * j + 3] = t.w;
    }
    const float4* l4 = reinterpret_cast<const float4*>(logit + (size_t)i * DLOG);  // 80B rows: 16B aligned
#pragma unroll
    for (int j = 0; j < 5; ++j) {
        float4 t = l4[j];
        v[64 + 4 * j + 0] = t.x; v[64 + 4 * j + 1] = t.y; v[64 + 4 * j + 2] = t.z; v[64 + 4 * j + 3] = t.w;
    }
    {
        float4 t = reinterpret_cast<const float4*>(pts + (size_t)i * DPTS)[0];
        v[84] = t.x; v[85] = t.y; v[86] = t.z; v[87] = t.w;
    }
    v[88] = proj[(size_t)i * 3 + 0];
    v[89] = proj[(size_t)i * 3 + 1];
    v[90] = proj[(size_t)i * 3 + 2];
    v[91] = 1.0f;  // count

    float* base = g_sums + (size_t)cs * SUMS_STRIDE;
#pragma unroll
    for (int j = 0; j < 23; ++j)
        red4(base + 4 * j, v[4 * j], v[4 * j + 1], v[4 * j + 2], v[4 * j + 3]);
}

// ---------------- 3: sums -> means (in place, count slot preserved) ----------------
__global__ void means_kernel() {
    int t = blockIdx.x * blockDim.x + threadIdx.x;
    const int total = 2 * NCLU * KRAW;
    if (t >= total) return;
    int cs = t / KRAW;
    int d = t - cs * KRAW;
    float* row = g_sums + (size_t)cs * SUMS_STRIDE;
    float cnt = row[91];
    float s = row[d];
    row[d] = (cnt > 0.f) ? s / cnt : 0.f;
}

// ---------------- GEMM tile constants ----------------
#define AS_STRIDE 130            // 128 points + pad (2-way conflict on fill, 8B-aligned pairs)
#define BS_STRIDE 258            // 128 weights duplicated (256) + pad
#define SMEM_FLOATS (KRAW * AS_STRIDE + KRAW * BS_STRIDE)
#define SMEM_BYTES (SMEM_FLOATS * 4)

// ---------------- 4: hc = W2 @ mean + b  (rows = 2C, K = 91) ----------------
__global__ __launch_bounds__(256, 1)
void hc_gemm_kernel(const float* __restrict__ W, const float* __restrict__ bias) {
    extern __shared__ float smem[];
    float* As = smem;                   // [k][p]  91 x 130
    float* Bs = smem + KRAW * AS_STRIDE;  // [k][2n dup] 91 x 258
    int tid = threadIdx.x;
    int tx = tid & 15, ty = tid >> 4;
    int row0 = blockIdx.x * 128;

    for (int i = tid; i < 128 * KRAW; i += 256) {
        int p = i / KRAW, k = i - p * KRAW;
        As[k * AS_STRIDE + p] = g_sums[(size_t)(row0 + p) * SUMS_STRIDE + k];
    }
    for (int i = tid; i < DOUT * KRAW; i += 256) {
        int n = i / KRAW, k = i - n * KRAW;
        float w = W[(size_t)n * 182 + 91 + k];
        int o = k * BS_STRIDE + 2 * n;
        Bs[o] = w; Bs[o + 1] = w;
    }
    __syncthreads();

    unsigned long long acc[4][8];
#pragma unroll
    for (int ip = 0; ip < 4; ++ip)
#pragma unroll
        for (int j = 0; j < 8; ++j) acc[ip][j] = 0ull;

    int aoff = ty * 8;
    int boff2 = tx * 16;
#pragma unroll 13
    for (int k = 0; k < KRAW; ++k) {
        const unsigned long long* ap =
            reinterpret_cast<const unsigned long long*>(As + k * AS_STRIDE + aoff);
        const unsigned long long* bp =
            reinterpret_cast<const unsigned long long*>(Bs + k * BS_STRIDE + boff2);
        unsigned long long a0 = ap[0], a1 = ap[1], a2 = ap[2], a3 = ap[3];
#pragma unroll
        for (int j = 0; j < 8; ++j) {
            unsigned long long bj = bp[j];
            acc[0][j] = fma2(a0, bj, acc[0][j]);
            acc[1][j] = fma2(a1, bj, acc[1][j]);
            acc[2][j] = fma2(a2, bj, acc[2][j]);
            acc[3][j] = fma2(a3, bj, acc[3][j]);
        }
    }

    int boff = tx * 8;
    float4 bA = reinterpret_cast<const float4*>(bias + boff)[0];
    float4 bB = reinterpret_cast<const float4*>(bias + boff)[1];
#pragma unroll
    for (int p = 0; p < 8; ++p) {
        int r = row0 + ty * 8 + p;   // always < 2C (80000 = 625*128)
        float hrow[8];
#pragma unroll
        for (int j = 0; j < 8; ++j) {
            float2 f = *reinterpret_cast<float2*>(&acc[p >> 1][j]);
            float v = (p & 1) ? f.y : f.x;
            v += (j < 4) ? (&bA.x)[j] : (&bB.x)[j - 4];
            hrow[j] = v;
        }
        float4* hp = reinterpret_cast<float4*>(g_hc + (size_t)r * DOUT + boff);
        hp[0] = make_float4(hrow[0], hrow[1], hrow[2], hrow[3]);
        hp[1] = make_float4(hrow[4], hrow[5], hrow[6], hrow[7]);
    }
}

// ---------------- 5: main GEMM h = W1 @ raw + hc[cs]  + BN partials ----------------
__global__ __launch_bounds__(256, 1)
void main_gemm_kernel(const float* __restrict__ feat,
                      const float* __restrict__ logit,
                      const float* __restrict__ pts,
                      const float* __restrict__ proj,
                      const int* __restrict__ idx,
                      const void* __restrict__ mask,
                      const float* __restrict__ W) {
    extern __shared__ float smem[];
    float* As = smem;
    float* Bs = smem + KRAW * AS_STRIDE;
    int tid = threadIdx.x;
    int tx = tid & 15, ty = tid >> 4;
    int row0 = blockIdx.x * 128;

    // stage raw features transposed: As[k][p]
    for (int i = tid; i < 128 * DFEAT; i += 256) {
        int p = i >> 6, d = i & 63;
        int r = row0 + p;
        As[d * AS_STRIDE + p] = (r < NPTS) ? feat[(size_t)r * DFEAT + d] : 0.f;
    }
    for (int i = tid; i < 128 * DLOG; i += 256) {
        int p = i / DLOG, d = i - p * DLOG;
        int r = row0 + p;
        As[(64 + d) * AS_STRIDE + p] = (r < NPTS) ? logit[(size_t)r * DLOG + d] : 0.f;
    }
    for (int i = tid; i < 128 * DPTS; i += 256) {
        int p = i >> 2, d = i & 3;
        int r = row0 + p;
        As[(84 + d) * AS_STRIDE + p] = (r < NPTS) ? pts[(size_t)r * DPTS + d] : 0.f;
    }
    for (int i = tid; i < 128 * DPROJ; i += 256) {
        int p = i / DPROJ, d = i - p * DPROJ;
        int r = row0 + p;
        As[(88 + d) * AS_STRIDE + p] = (r < NPTS) ? proj[(size_t)r * DPROJ + d] : 0.f;
    }
    // stage W1 duplicated: Bs[k][2n]=Bs[k][2n+1]=W[n][k]
    for (int i = tid; i < DOUT * KRAW; i += 256) {
        int n = i / KRAW, k = i - n * KRAW;
        float w = W[(size_t)n * 182 + k];
        int o = k * BS_STRIDE + 2 * n;
        Bs[o] = w; Bs[o + 1] = w;
    }
    __syncthreads();

    unsigned long long acc[4][8];
#pragma unroll
    for (int ip = 0; ip < 4; ++ip)
#pragma unroll
        for (int j = 0; j < 8; ++j) acc[ip][j] = 0ull;

    int aoff = ty * 8;
    int boff2 = tx * 16;
#pragma unroll 13
    for (int k = 0; k < KRAW; ++k) {
        const unsigned long long* ap =
            reinterpret_cast<const unsigned long long*>(As + k * AS_STRIDE + aoff);
        const unsigned long long* bp =
            reinterpret_cast<const unsigned long long*>(Bs + k * BS_STRIDE + boff2);
        unsigned long long a0 = ap[0], a1 = ap[1], a2 = ap[2], a3 = ap[3];
#pragma unroll
        for (int j = 0; j < 8; ++j) {
            unsigned long long bj = bp[j];
            acc[0][j] = fma2(a0, bj, acc[0][j]);
            acc[1][j] = fma2(a1, bj, acc[1][j]);
            acc[2][j] = fma2(a2, bj, acc[2][j]);
            acc[3][j] = fma2(a3, bj, acc[3][j]);
        }
    }

    // epilogue: add hc[cluster,side], write h, accumulate BN partials
    int mode = g_maskmode;
    int boff = tx * 8;
    float s_[8], q_[8];
#pragma unroll
    for (int j = 0; j < 8; ++j) { s_[j] = 0.f; q_[j] = 0.f; }

#pragma unroll
    for (int p = 0; p < 8; ++p) {
        int r = row0 + ty * 8 + p;
        if (r < NPTS) {
            int fg = get_fg(mask, r, mode);
            int cs = (fg ? 0 : NCLU) + idx[r];
            const float4* hcp = reinterpret_cast<const float4*>(g_hc + (size_t)cs * DOUT + boff);
            float4 hA = hcp[0], hB = hcp[1];
            float hrow[8];
#pragma unroll
            for (int j = 0; j < 8; ++j) {
                float2 f = *reinterpret_cast<float2*>(&acc[p >> 1][j]);
                float v = (p & 1) ? f.y : f.x;
                v += (j < 4) ? (&hA.x)[j] : (&hB.x)[j - 4];
                hrow[j] = v;
                s_[j] += v;
                q_[j] += v * v;
            }
            float4* hp = reinterpret_cast<float4*>(g_h + (size_t)r * DOUT + boff);
            hp[0] = make_float4(hrow[0], hrow[1], hrow[2], hrow[3]);
            hp[1] = make_float4(hrow[4], hrow[5], hrow[6], hrow[7]);
        }
    }

    // block-level BN reduction (reuse As region)
    __syncthreads();
    float* red = smem;  // 16 x 128 floats
#pragma unroll
    for (int j = 0; j < 8; ++j) red[ty * 128 + boff + j] = s_[j];
    __syncthreads();
    if (tid < 128) {
        float t = 0.f;
#pragma unroll
        for (int r = 0; r < 16; ++r) t += red[r * 128 + tid];
        atomicAdd(&g_bnsum[tid], t);
    }
    __syncthreads();
#pragma unroll
    for (int j = 0; j < 8; ++j) red[ty * 128 + boff + j] = q_[j];
    __syncthreads();
    if (tid < 128) {
        float t = 0.f;
#pragma unroll
        for (int r = 0; r < 16; ++r) t += red[r * 128 + tid];
        atomicAdd(&g_bnsq[tid], t);
    }
}

// ---------------- 6: BN finalize ----------------
__global__ void bn_finalize_kernel(const float* __restrict__ gamma,
                                   const float* __restrict__ beta) {
    int d = threadIdx.x;
    const float invN = 1.0f / (float)NPTS;
    float mu = g_bnsum[d] * invN;
    float var = g_bnsq[d] * invN - mu * mu;
    if (var < 0.f) var = 0.f;
    float sc = gamma[d] * rsqrtf(var + EPS);
    g_scale[d] = sc;
    g_shift[d] = beta[d] - mu * sc;
}

// ---------------- 7: normalize + leaky relu ----------------
__global__ void map_kernel(float* __restrict__ out) {
    __shared__ float sc[DOUT], sh[DOUT];
    if (threadIdx.x < DOUT) {
        sc[threadIdx.x] = g_scale[threadIdx.x];
        sh[threadIdx.x] = g_shift[threadIdx.x];
    }
    __syncthreads();
    size_t gid = (size_t)blockIdx.x * blockDim.x + threadIdx.x;  // over float4s; grid sized exactly
    int d = ((int)(gid & 31)) * 4;
    float4 h = reinterpret_cast<const float4*>(g_h)[gid];
    float4 r;
    float v;
    v = h.x * sc[d + 0] + sh[d + 0]; r.x = (v >= 0.f) ? v : SLOPE * v;
    v = h.y * sc[d + 1] + sh[d + 1]; r.y = (v >= 0.f) ? v : SLOPE * v;
    v = h.z * sc[d + 2] + sh[d + 2]; r.z = (v >= 0.f) ? v : SLOPE * v;
    v = h.w * sc[d + 3] + sh[d + 3]; r.w = (v >= 0.f) ? v : SLOPE * v;
    reinterpret_cast<float4*>(out)[gid] = r;
}

// ---------------- launch ----------------
extern "C" void kernel_launch(void* const* d_in, const int* in_sizes, int n_in,
                              void* d_out, int out_size) {
    const float* points = (const float*)d_in[0];
    const float* proj   = (const float*)d_in[1];
    const float* feat   = (const float*)d_in[2];
    const float* logits = (const float*)d_in[3];
    const int*   idx    = (const int*)d_in[4];
    const void*  mask   = d_in[5];
    const float* W      = (const float*)d_in[6];
    const float* bias   = (const float*)d_in[7];
    const float* gamma  = (const float*)d_in[8];
    const float* beta   = (const float*)d_in[9];
    float* out = (float*)d_out;

    cudaFuncSetAttribute(hc_gemm_kernel, cudaFuncAttributeMaxDynamicSharedMemorySize, SMEM_BYTES);
    cudaFuncSetAttribute(main_gemm_kernel, cudaFuncAttributeMaxDynamicSharedMemorySize, SMEM_BYTES);

    probe_mask_kernel<<<1, 256>>>((const unsigned char*)mask);

    {
        const size_t n4 = (size_t)2 * NCLU * SUMS_STRIDE / 4;
        int blocks = (int)((n4 + 255) / 256);
        zero_kernel<<<blocks, 256>>>();
    }

    scatter_kernel<<<(NPTS + 255) / 256, 256>>>(feat, logits, points, proj, idx, mask);

    {
        int total = 2 * NCLU * KRAW;
        means_kernel<<<(total + 255) / 256, 256>>>();
    }

    hc_gemm_kernel<<<2 * NCLU / 128, 256, SMEM_BYTES>>>(W, bias);

    main_gemm_kernel<<<(NPTS + 127) / 128, 256, SMEM_BYTES>>>(feat, logits, points, proj,
                                                              idx, mask, W);

    bn_finalize_kernel<<<1, DOUT>>>(gamma, beta);

    {
        size_t total4 = (size_t)NPTS * DOUT / 4;  // 16,000,000
        map_kernel<<<(unsigned)(total4 / 256), 256>>>(out);
    }
}

// round 2
// speedup vs baseline: 3.0435x; 3.0435x over previous
#include <cuda_runtime.h>
#include <cuda_bf16.h>
#include <cstdint>

#define NPTS 500000
#define NCLU 40000
#define DFEAT 64
#define DLOG 20
#define DPTS 4
#define DPROJ 3
#define KRAW 91            // 64+20+4+3
#define DOUT 128
#define SUMS_STRIDE 96     // 91 sums + count at [91], padded to 96
#define EPS 1e-5f
#define SLOPE 0.1f

// ---------------- device scratch (static, allocation-free) ----------------
__device__ float g_sums[2ull * NCLU * SUMS_STRIDE];   // per (side,cluster): sums[0..90], count[91]
__device__ float g_hc[2ull * NCLU * DOUT];            // W2 @ mean + b  per (side,cluster)
__device__ float g_h[(size_t)NPTS * DOUT];            // pre-BN activations
__device__ float g_Wt[2 * KRAW * DOUT];               // W transposed: [half][k][n]
__device__ float g_bnsum[DOUT];
__device__ float g_bnsq[DOUT];
__device__ float g_scale[DOUT];
__device__ float g_shift[DOUT];
__device__ int   g_maskmode;                          // 0=uint8(bool), 1=float32, 2=int32

// ---------------- helpers ----------------
__device__ __forceinline__ unsigned long long fma2(unsigned long long a,
                                                   unsigned long long b,
                                                   unsigned long long c) {
    unsigned long long d;
    asm("fma.rn.f32x2 %0, %1, %2, %3;" : "=l"(d) : "l"(a), "l"(b), "l"(c));
    return d;
}

__device__ __forceinline__ unsigned long long dup2(float v) {
    unsigned long long d;
    asm("mov.b64 %0, {%1, %1};" : "=l"(d) : "f"(v));
    return d;
}

__device__ __forceinline__ void red4(float* p, float a, float b, float c, float d) {
    asm volatile("red.global.add.v4.f32 [%0], {%1, %2, %3, %4};"
                 :: "l"(p), "f"(a), "f"(b), "f"(c), "f"(d) : "memory");
}

__device__ __forceinline__ int get_fg(const void* m, int i, int mode) {
    if (mode == 0) return ((const unsigned char*)m)[i] != 0;
    if (mode == 1) return ((const float*)m)[i] != 0.0f;
    return ((const int*)m)[i] != 0;
}

// ---------------- 0: probe fg_mask dtype ----------------
__global__ void probe_mask_kernel(const unsigned char* m) {
    __shared__ int s1, s3;
    if (threadIdx.x == 0) { s1 = 0; s3 = 0; }
    __syncthreads();
    int o1 = 0, o3 = 0;
    for (int i = threadIdx.x; i < 16384; i += blockDim.x) {
        o1 |= m[i * 4 + 1];
        o3 |= m[i * 4 + 3];
    }
    atomicOr(&s1, o1);
    atomicOr(&s3, o3);
    __syncthreads();
    if (threadIdx.x == 0) g_maskmode = s1 ? 0 : (s3 ? 1 : 2);
}

// ---------------- 0b: transpose W into [half][k][n] ----------------
__global__ void prep_w_kernel(const float* __restrict__ W) {
    int t = blockIdx.x * blockDim.x + threadIdx.x;
    const int total = 2 * KRAW * DOUT;
    if (t >= total) return;
    int h = t / (KRAW * DOUT);
    int r = t - h * (KRAW * DOUT);
    int k = r >> 7;
    int n = r & 127;
    g_Wt[t] = W[(size_t)n * 182 + h * KRAW + k];
}

// ---------------- 1: zero scratch ----------------
__global__ void zero_kernel() {
    size_t gid = (size_t)blockIdx.x * blockDim.x + threadIdx.x;
    const size_t n4 = (size_t)2 * NCLU * SUMS_STRIDE / 4;
    float4 z = make_float4(0.f, 0.f, 0.f, 0.f);
    if (gid < n4) reinterpret_cast<float4*>(g_sums)[gid] = z;
    if (gid < 32) reinterpret_cast<float4*>(g_bnsum)[gid] = z;
    else if (gid < 64) reinterpret_cast<float4*>(g_bnsq)[gid - 32] = z;
}

// ---------------- 2: scatter segment sums ----------------
__global__ void scatter_kernel(const float* __restrict__ feat,
                               const float* __restrict__ logit,
                               const float* __restrict__ pts,
                               const float* __restrict__ proj,
                               const int* __restrict__ idx,
                               const void* __restrict__ mask) {
    int i = blockIdx.x * blockDim.x + threadIdx.x;
    if (i >= NPTS) return;
    int mode = g_maskmode;
    int fg = get_fg(mask, i, mode);
    int cs = (fg ? 0 : NCLU) + idx[i];

    float v[92];
    const float4* f4 = reinterpret_cast<const float4*>(feat + (size_t)i * DFEAT);
#pragma unroll
    for (int j = 0; j < 16; ++j) {
        float4 t = f4[j];
        v[4 * j + 0] = t.x; v[4 * j + 1] = t.y; v[4 * j + 2] = t.z; v[4 * j + 3] = t.w;
    }
    const float4* l4 = reinterpret_cast<const float4*>(logit + (size_t)i * DLOG);
#pragma unroll
    for (int j = 0; j < 5; ++j) {
        float4 t = l4[j];
        v[64 + 4 * j + 0] = t.x; v[64 + 4 * j + 1] = t.y; v[64 + 4 * j + 2] = t.z; v[64 + 4 * j + 3] = t.w;
    }
    {
        float4 t = reinterpret_cast<const float4*>(pts + (size_t)i * DPTS)[0];
        v[84] = t.x; v[85] = t.y; v[86] = t.z; v[87] = t.w;
    }
    v[88] = proj[(size_t)i * 3 + 0];
    v[89] = proj[(size_t)i * 3 + 1];
    v[90] = proj[(size_t)i * 3 + 2];
    v[91] = 1.0f;  // count

    float* base = g_sums + (size_t)cs * SUMS_STRIDE;
#pragma unroll
    for (int j = 0; j < 23; ++j)
        red4(base + 4 * j, v[4 * j], v[4 * j + 1], v[4 * j + 2], v[4 * j + 3]);
}

// ---------------- 3: sums -> means (in place, vectorized) ----------------
__global__ void means_kernel() {
    int t = blockIdx.x * blockDim.x + threadIdx.x;
    const int total = 2 * NCLU * 23;   // 23 float4s cover floats 0..91
    if (t >= total) return;
    int cs = t / 23;
    int q = t - cs * 23;
    float* row = g_sums + (size_t)cs * SUMS_STRIDE;
    float cnt = row[91];
    float inv = (cnt > 0.f) ? 1.0f / cnt : 0.0f;
    float4* p = reinterpret_cast<float4*>(row) + q;
    float4 v = *p;
    v.x *= inv; v.y *= inv; v.z *= inv; v.w *= inv;   // count slot scaled too; never read again
    *p = v;
}

// ---------------- GEMM tile constants ----------------
#define AS_STRIDE 92             // A row-major [p][k], 91+1
#define BS_STRIDE 132            // B [k][n], 128 + 4 pad (16B aligned rows)
#define SMEM_FLOATS (128 * AS_STRIDE + KRAW * BS_STRIDE)
#define SMEM_BYTES (SMEM_FLOATS * 4)

// shared mainloop: acc[p][j] covers point (ty*8+p), outputs (tx*8 + 2j, +1)
__device__ __forceinline__ void gemm_mainloop(const float* As, const float* Bs,
                                              int tx, int ty,
                                              unsigned long long acc[8][4]) {
#pragma unroll
    for (int p = 0; p < 8; ++p)
#pragma unroll
        for (int j = 0; j < 4; ++j) acc[p][j] = 0ull;

#pragma unroll 7
    for (int k = 0; k < KRAW; ++k) {
        const ulonglong2* bp =
            reinterpret_cast<const ulonglong2*>(Bs + k * BS_STRIDE + tx * 8);
        ulonglong2 bb0 = bp[0];
        ulonglong2 bb1 = bp[1];
        unsigned long long b0 = bb0.x, b1 = bb0.y, b2 = bb1.x, b3 = bb1.y;
        const float* ap = As + (ty * 8) * AS_STRIDE + k;
#pragma unroll
        for (int p = 0; p < 8; ++p) {
            unsigned long long ad = dup2(ap[p * AS_STRIDE]);
            acc[p][0] = fma2(ad, b0, acc[p][0]);
            acc[p][1] = fma2(ad, b1, acc[p][1]);
            acc[p][2] = fma2(ad, b2, acc[p][2]);
            acc[p][3] = fma2(ad, b3, acc[p][3]);
        }
    }
}

// ---------------- 4: hc = W2 @ mean + b  (rows = 2C, K = 91) ----------------
__global__ __launch_bounds__(256)
void hc_gemm_kernel(const float* __restrict__ bias) {
    extern __shared__ float smem[];
    float* As = smem;                       // [p][k] 128 x 92
    float* Bs = smem + 128 * AS_STRIDE;     // [k][n] 91 x 132
    int tid = threadIdx.x;
    int tx = tid & 15, ty = tid >> 4;
    int row0 = blockIdx.x * 128;

    // A fill: coalesced read, conflict-free write (lanes -> consecutive k)
    for (int i = tid; i < 128 * AS_STRIDE; i += 256) {
        int p = i / AS_STRIDE, k = i - p * AS_STRIDE;
        As[i] = g_sums[(size_t)(row0 + p) * SUMS_STRIDE + k];  // k=91 copies count, unused
    }
    // B fill from pre-transposed W (second half)
    const float* Wt = g_Wt + KRAW * DOUT;
    for (int i = tid; i < KRAW * DOUT; i += 256) {
        int k = i >> 7, n = i & 127;
        Bs[k * BS_STRIDE + n] = Wt[i];
    }
    __syncthreads();

    unsigned long long acc[8][4];
    gemm_mainloop(As, Bs, tx, ty, acc);

    int boff = tx * 8;
    float4 bA = reinterpret_cast<const float4*>(bias + boff)[0];
    float4 bB = reinterpret_cast<const float4*>(bias + boff)[1];
#pragma unroll
    for (int p = 0; p < 8; ++p) {
        int r = row0 + ty * 8 + p;   // always < 80000 = 625*128
        float hrow[8];
#pragma unroll
        for (int j = 0; j < 4; ++j) {
            float2 f = *reinterpret_cast<float2*>(&acc[p][j]);
            hrow[2 * j] = f.x;
            hrow[2 * j + 1] = f.y;
        }
#pragma unroll
        for (int j = 0; j < 8; ++j)
            hrow[j] += (j < 4) ? (&bA.x)[j] : (&bB.x)[j - 4];
        float4* hp = reinterpret_cast<float4*>(g_hc + (size_t)r * DOUT + boff);
        hp[0] = make_float4(hrow[0], hrow[1], hrow[2], hrow[3]);
        hp[1] = make_float4(hrow[4], hrow[5], hrow[6], hrow[7]);
    }
}

// ---------------- 5: main GEMM h = W1 @ raw + hc[cs]  + BN partials ----------------
__global__ __launch_bounds__(256)
void main_gemm_kernel(const float* __restrict__ feat,
                      const float* __restrict__ logit,
                      const float* __restrict__ pts,
                      const float* __restrict__ proj,
                      const int* __restrict__ idx,
                      const void* __restrict__ mask) {
    extern __shared__ float smem[];
    float* As = smem;
    float* Bs = smem + 128 * AS_STRIDE;
    int tid = threadIdx.x;
    int tx = tid & 15, ty = tid >> 4;
    int row0 = blockIdx.x * 128;

    // stage raw features row-major As[p][k]; all writes lane-consecutive (conflict-free)
    for (int i = tid; i < 128 * DFEAT; i += 256) {
        int p = i >> 6, d = i & 63;
        int r = row0 + p;
        As[p * AS_STRIDE + d] = (r < NPTS) ? feat[(size_t)r * DFEAT + d] : 0.f;
    }
    for (int i = tid; i < 128 * DLOG; i += 256) {
        int p = i / DLOG, d = i - p * DLOG;
        int r = row0 + p;
        As[p * AS_STRIDE + 64 + d] = (r < NPTS) ? logit[(size_t)r * DLOG + d] : 0.f;
    }
    for (int i = tid; i < 128 * DPTS; i += 256) {
        int p = i >> 2, d = i & 3;
        int r = row0 + p;
        As[p * AS_STRIDE + 84 + d] = (r < NPTS) ? pts[(size_t)r * DPTS + d] : 0.f;
    }
    for (int i = tid; i < 128 * DPROJ; i += 256) {
        int p = i / DPROJ, d = i - p * DPROJ;
        int r = row0 + p;
        As[p * AS_STRIDE + 88 + d] = (r < NPTS) ? proj[(size_t)r * DPROJ + d] : 0.f;
    }
    // B fill from pre-transposed W (first half)
    for (int i = tid; i < KRAW * DOUT; i += 256) {
        int k = i >> 7, n = i & 127;
        Bs[k * BS_STRIDE + n] = g_Wt[i];
    }
    __syncthreads();

    unsigned long long acc[8][4];
    gemm_mainloop(As, Bs, tx, ty, acc);

    // epilogue: add hc[cluster,side], write h, accumulate BN partials
    int mode = g_maskmode;
    int boff = tx * 8;
    float s_[8], q_[8];
#pragma unroll
    for (int j = 0; j < 8; ++j) { s_[j] = 0.f; q_[j] = 0.f; }

#pragma unroll
    for (int p = 0; p < 8; ++p) {
        int r = row0 + ty * 8 + p;
        if (r < NPTS) {
            int fg = get_fg(mask, r, mode);
            int cs = (fg ? 0 : NCLU) + idx[r];
            const float4* hcp = reinterpret_cast<const float4*>(g_hc + (size_t)cs * DOUT + boff);
            float4 hA = hcp[0], hB = hcp[1];
            float hrow[8];
#pragma unroll
            for (int j = 0; j < 4; ++j) {
                float2 f = *reinterpret_cast<float2*>(&acc[p][j]);
                hrow[2 * j] = f.x;
                hrow[2 * j + 1] = f.y;
            }
#pragma unroll
            for (int j = 0; j < 8; ++j) {
                float v = hrow[j] + ((j < 4) ? (&hA.x)[j] : (&hB.x)[j - 4]);
                hrow[j] = v;
                s_[j] += v;
                q_[j] += v * v;
            }
            float4* hp = reinterpret_cast<float4*>(g_h + (size_t)r * DOUT + boff);
            hp[0] = make_float4(hrow[0], hrow[1], hrow[2], hrow[3]);
            hp[1] = make_float4(hrow[4], hrow[5], hrow[6], hrow[7]);
        }
    }

    // block-level BN reduction (reuse As region)
    __syncthreads();
    float* red = smem;  // 16 x 128 floats
#pragma unroll
    for (int j = 0; j < 8; ++j) red[ty * 128 + boff + j] = s_[j];
    __syncthreads();
    if (tid < 128) {
        float t = 0.f;
#pragma unroll
        for (int r = 0; r < 16; ++r) t += red[r * 128 + tid];
        atomicAdd(&g_bnsum[tid], t);
    }
    __syncthreads();
#pragma unroll
    for (int j = 0; j < 8; ++j) red[ty * 128 + boff + j] = q_[j];
    __syncthreads();
    if (tid < 128) {
        float t = 0.f;
#pragma unroll
        for (int r = 0; r < 16; ++r) t += red[r * 128 + tid];
        atomicAdd(&g_bnsq[tid], t);
    }
}

// ---------------- 6: BN finalize ----------------
__global__ void bn_finalize_kernel(const float* __restrict__ gamma,
                                   const float* __restrict__ beta) {
    int d = threadIdx.x;
    const float invN = 1.0f / (float)NPTS;
    float mu = g_bnsum[d] * invN;
    float var = g_bnsq[d] * invN - mu * mu;
    if (var < 0.f) var = 0.f;
    float sc = gamma[d] * rsqrtf(var + EPS);
    g_scale[d] = sc;
    g_shift[d] = beta[d] - mu * sc;
}

// ---------------- 7: normalize + leaky relu ----------------
__global__ void map_kernel(float* __restrict__ out) {
    __shared__ float sc[DOUT], sh[DOUT];
    if (threadIdx.x < DOUT) {
        sc[threadIdx.x] = g_scale[threadIdx.x];
        sh[threadIdx.x] = g_shift[threadIdx.x];
    }
    __syncthreads();
    size_t gid = (size_t)blockIdx.x * blockDim.x + threadIdx.x;
    int d = ((int)(gid & 31)) * 4;
    float4 h = reinterpret_cast<const float4*>(g_h)[gid];
    float4 r;
    float v;
    v = h.x * sc[d + 0] + sh[d + 0]; r.x = (v >= 0.f) ? v : SLOPE * v;
    v = h.y * sc[d + 1] + sh[d + 1]; r.y = (v >= 0.f) ? v : SLOPE * v;
    v = h.z * sc[d + 2] + sh[d + 2]; r.z = (v >= 0.f) ? v : SLOPE * v;
    v = h.w * sc[d + 3] + sh[d + 3]; r.w = (v >= 0.f) ? v : SLOPE * v;
    reinterpret_cast<float4*>(out)[gid] = r;
}

// ---------------- launch ----------------
extern "C" void kernel_launch(void* const* d_in, const int* in_sizes, int n_in,
                              void* d_out, int out_size) {
    const float* points = (const float*)d_in[0];
    const float* proj   = (const float*)d_in[1];
    const float* feat   = (const float*)d_in[2];
    const float* logits = (const float*)d_in[3];
    const int*   idx    = (const int*)d_in[4];
    const void*  mask   = d_in[5];
    const float* W      = (const float*)d_in[6];
    const float* bias   = (const float*)d_in[7];
    const float* gamma  = (const float*)d_in[8];
    const float* beta   = (const float*)d_in[9];
    float* out = (float*)d_out;

    cudaFuncSetAttribute(hc_gemm_kernel, cudaFuncAttributeMaxDynamicSharedMemorySize, SMEM_BYTES);
    cudaFuncSetAttribute(main_gemm_kernel, cudaFuncAttributeMaxDynamicSharedMemorySize, SMEM_BYTES);

    probe_mask_kernel<<<1, 256>>>((const unsigned char*)mask);
    prep_w_kernel<<<(2 * KRAW * DOUT + 255) / 256, 256>>>(W);

    {
        const size_t n4 = (size_t)2 * NCLU * SUMS_STRIDE / 4;
        int blocks = (int)((n4 + 255) / 256);
        zero_kernel<<<blocks, 256>>>();
    }

    scatter_kernel<<<(NPTS + 255) / 256, 256>>>(feat, logits, points, proj, idx, mask);

    {
        int total = 2 * NCLU * 23;
        means_kernel<<<(total + 255) / 256, 256>>>();
    }

    hc_gemm_kernel<<<2 * NCLU / 128, 256, SMEM_BYTES>>>(bias);

    main_gemm_kernel<<<(NPTS + 127) / 128, 256, SMEM_BYTES>>>(feat, logits, points, proj,
                                                              idx, mask);

    bn_finalize_kernel<<<1, DOUT>>>(gamma, beta);

    {
        size_t total4 = (size_t)NPTS * DOUT / 4;  // 16,000,000
        map_kernel<<<(unsigned)(total4 / 256), 256>>>(out);
    }
}